// round 16
// baseline (speedup 1.0000x reference)
#include <cuda_runtime.h>
#include <cuda_fp16.h>
#include <math.h>
#include <stdint.h>

#define B_  2
#define S_  512
#define N_  20000
#define D_  384
#define H_  3
#define C_  128
#define F_  384
#define E_  320000
#define DG_ 128
#define BN_ (B_*N_)
#define BE_ (B_*E_)

#define NW_      768
#define TOTCH_MM2 625                  // 20000/32 exactly
#define NSPLIT_MM2 36                  // 2x4x36 = 288 CTAs = one wave
#define STG_A    10240                 // 128*40*2
#define STG_B    8704                  // 32*136*2
#define STG_SZ   (STG_A+STG_B)         // 18944
#define SMEM_MMA (4*STG_SZ)            // 75776

// ---------------- device scratch ----------------
__device__ __align__(16) __half g_Y2[512*NW_];                 // fp16 single
__device__ __align__(16) __half g_Wq2[(size_t)N_*512];         // fp16 single
__device__ __align__(16) __half g_Wp2[(size_t)S_*N_];          // fp16 single [512,20000]
__device__ __align__(16) __half g_WtT[F_*DG_];                 // Wtemp^T fp16 [384,128]
__device__ __align__(16) __half g_gat2[(size_t)BN_*F_];        // gat fp16 node-major [40000,384]
__device__ __align__(16) __half g_xq[(size_t)N_*256];          // gat@Wtemp^T fp16 [20000, b*128+dg]
__device__ __align__(16) __half g_xp[(size_t)BN_*F_];          // fp16
__device__ float g_out2[B_*S_*DG_];                            // mm2 accumulator
__device__ float g_wsum[DG_];                                  // rowsum(Wtemp)
__device__ float g_uvw[3*F_];
__device__ float g_asrc[BN_*H_];
__device__ float g_adst[BN_*H_];
__device__ int   g_off[BN_+1];
__device__ int   g_cnt[BN_];
__device__ int   g_cur[BN_];
__device__ int   g_esrc[BE_];

__device__ __forceinline__ float lrelu(float x){ return x > 0.f ? x : 0.2f*x; }
__device__ __forceinline__ unsigned su(const void* p){
    return (unsigned)__cvta_generic_to_shared(p);
}
__device__ __forceinline__ void cpa16(unsigned dst, const void* src, bool pred){
    int sz = pred ? 16 : 0;
    asm volatile("cp.async.cg.shared.global [%0], [%1], 16, %2;\n"
                 :: "r"(dst), "l"(src), "r"(sz));
}
__device__ __forceinline__ void ldsm4(unsigned addr, unsigned &r0, unsigned &r1, unsigned &r2, unsigned &r3){
    asm volatile("ldmatrix.sync.aligned.m8n8.x4.shared.b16 {%0,%1,%2,%3}, [%4];\n"
                 : "=r"(r0),"=r"(r1),"=r"(r2),"=r"(r3) : "r"(addr));
}
__device__ __forceinline__ void ldsm4t(unsigned addr, unsigned &r0, unsigned &r1, unsigned &r2, unsigned &r3){
    asm volatile("ldmatrix.sync.aligned.m8n8.x4.trans.shared.b16 {%0,%1,%2,%3}, [%4];\n"
                 : "=r"(r0),"=r"(r1),"=r"(r2),"=r"(r3) : "r"(addr));
}
__device__ __forceinline__ void mma16816(float* c, const unsigned* a, const unsigned* b){
    asm volatile("mma.sync.aligned.m16n8k16.row.col.f32.f16.f16.f32 "
                 "{%0,%1,%2,%3},{%4,%5,%6,%7},{%8,%9},{%0,%1,%2,%3};\n"
                 : "+f"(c[0]),"+f"(c[1]),"+f"(c[2]),"+f"(c[3])
                 : "r"(a[0]),"r"(a[1]),"r"(a[2]),"r"(a[3]),"r"(b[0]),"r"(b[1]));
}

// ---------------- mega setup ----------------
#define CVTWQ_T (N_*(S_/4))            // 2,560,000
#define CVTWP_T (S_*(N_/4))            // 2,560,000
__global__ void k_setup(const float* __restrict__ Wlin, const float* __restrict__ Wm,
                        const float* __restrict__ bm, const float* __restrict__ Wq,
                        const float* __restrict__ Wproj, const float* __restrict__ Wtemp){
    int i = blockIdx.x*blockDim.x + threadIdx.x;
    if (i < F_){
        float u=0.f, v=0.f, w=0.f;
        for (int d = 0; d < D_; d++){
            float wl = Wlin[i*D_ + d];
            u += wl*Wm[d]; v += wl*bm[d]; w += wl;
        }
        g_uvw[i]=u; g_uvw[F_+i]=v; g_uvw[2*F_+i]=w;
    }
    if (i < DG_){
        float s = 0.f;
        for (int f = 0; f < F_; f++) s += Wtemp[i*F_ + f];
        g_wsum[i] = s;
    }
    if (i < F_*DG_){
        int f = i >> 7, dg = i & 127;
        g_WtT[f*DG_ + dg] = __float2half_rn(Wtemp[dg*F_ + f]);
    }
    if (i < B_*S_*DG_) g_out2[i] = 0.f;
    if (i < BN_){ g_cnt[i] = 0; g_cur[i] = 0; }
    if (i < BN_*H_){ g_asrc[i] = 0.f; g_adst[i] = 0.f; }
    if (i < CVTWQ_T){
        int m = i >> 7, k = (i & 127) << 2;
        float4 x = *(const float4*)(Wq + (size_t)m*S_ + k);
        union { __half b[4]; uint2 u; } hh;
        hh.b[0] = __float2half_rn(x.x);
        hh.b[1] = __float2half_rn(x.y);
        hh.b[2] = __float2half_rn(x.z);
        hh.b[3] = __float2half_rn(x.w);
        *(uint2*)&g_Wq2[(size_t)m*512 + k] = hh.u;
    }
    if (i < CVTWP_T){
        int m = i / (N_/4), k = (i % (N_/4)) << 2;
        float4 x = *(const float4*)(Wproj + (size_t)m*N_ + k);
        union { __half b[4]; uint2 u; } hh;
        hh.b[0] = __float2half_rn(x.x);
        hh.b[1] = __float2half_rn(x.y);
        hh.b[2] = __float2half_rn(x.z);
        hh.b[3] = __float2half_rn(x.w);
        *(uint2*)&g_Wp2[(size_t)m*N_ + k] = hh.u;
    }
}

// ---------------- fp32 tiled GEMM (Y only), C = A @ Bm^T -> fp16 ----------------
__global__ void k_gemm_bt(const float* __restrict__ A, int strideA,
                          const float* __restrict__ Bm,
                          int K, int Ncol, __half* __restrict__ Ysplit){
    const float* Ab = A + blockIdx.z * strideA;
    int m0 = blockIdx.y*64, n0 = blockIdx.x*64;
    __shared__ float As[16][64];
    __shared__ float Bs[16][64];
    int tid = threadIdx.x;
    int tm = tid >> 4, tn = tid & 15;
    int lrow = tid >> 2, lcol = (tid & 3)*4;
    float acc[4][4] = {};
    for (int k0 = 0; k0 < K; k0 += 16){
        float4 av = *(const float4*)(Ab + (m0+lrow)*K + k0 + lcol);
        As[lcol+0][lrow]=av.x; As[lcol+1][lrow]=av.y; As[lcol+2][lrow]=av.z; As[lcol+3][lrow]=av.w;
        float4 bv = *(const float4*)(Bm + (n0+lrow)*K + k0 + lcol);
        Bs[lcol+0][lrow]=bv.x; Bs[lcol+1][lrow]=bv.y; Bs[lcol+2][lrow]=bv.z; Bs[lcol+3][lrow]=bv.w;
        __syncthreads();
        #pragma unroll
        for (int kk = 0; kk < 16; kk++){
            float4 a4 = *(const float4*)&As[kk][tm*4];
            float4 b4 = *(const float4*)&Bs[kk][tn*4];
            float ar[4]={a4.x,a4.y,a4.z,a4.w}, br[4]={b4.x,b4.y,b4.z,b4.w};
            #pragma unroll
            for (int i=0;i<4;i++)
                #pragma unroll
                for (int j=0;j<4;j++) acc[i][j]=fmaf(ar[i],br[j],acc[i][j]);
        }
        __syncthreads();
    }
    #pragma unroll
    for (int i=0;i<4;i++){
        int row = m0 + tm*4 + i;
        #pragma unroll
        for (int j=0;j<4;j++){
            int col = n0 + tn*4 + j;
            int gc = blockIdx.z*384 + col;
            Ysplit[(size_t)row*NW_ + gc] = __float2half_rn(acc[i][j]);
        }
    }
}

// ---------------- fp16 mma.sync GEMM, 128x128 CTA, 64x64 warps, 4-stage, frag dbuf ----
// EPI=0: xp (fused affine + attention dots), ldb=768
// EPI=2: mm1 gat@Wtemp^T -> g_xq fp16, ldb=128
// EPI=3: mm2 Wproj@xq -> atomicAdd g_out2, ldb=256
template<int EPI>
__global__ __launch_bounds__(128, 2)
void k_mma(const __half* __restrict__ A, int lda, int M,
           const __half* __restrict__ Bm, int ldb,
           int totch, int nsplit,
           const float* __restrict__ bq, const float* __restrict__ mask,
           const float* __restrict__ att_src, const float* __restrict__ att_dst)
{
    extern __shared__ __align__(16) char smem[];
    uint32_t sbase = su(smem);

    const int tid = threadIdx.x, lane = tid & 31, wid = tid >> 5;
    const int wm = wid & 1, wn = wid >> 1;
    const int m0 = blockIdx.y*128, n0 = blockIdx.x*128;
    const int cbeg = (blockIdx.z * totch) / nsplit;
    const int cend = ((blockIdx.z + 1) * totch) / nsplit;
    const int nchunks = cend - cbeg;
    const int kbeg = cbeg * 32;
    const int lrow = lane & 15, lhi = lane >> 4;

    auto load_stage = [&](int s, int c){
        int kv = kbeg + c*32;
        uint32_t ab = sbase + s*STG_SZ;
        uint32_t bb = ab + STG_A;
        #pragma unroll
        for (int i = tid; i < 512; i += 128){
            int row = i >> 2, seg = i & 3;
            int gr = m0 + row;
            const void* src = A + (size_t)(gr < M ? gr : M-1)*lda + kv + seg*8;
            cpa16(ab + (uint32_t)(row*80 + seg*16), src, gr < M);
        }
        #pragma unroll
        for (int i = tid; i < 512; i += 128){
            int row = i >> 4, seg = i & 15;
            const void* src = Bm + (size_t)(kv + row)*ldb + n0 + seg*8;
            cpa16(bb + (uint32_t)(row*272 + seg*16), src, true);
        }
    };

    unsigned afr[2][4][4], bfr[2][8][2];
    auto ldfr = [&](int s, int kk, int buf){
        uint32_t ab = sbase + s*STG_SZ;
        uint32_t bb = ab + STG_A;
        int k0 = kk*16;
        #pragma unroll
        for (int mi = 0; mi < 4; ++mi){
            unsigned addr = ab + (uint32_t)((wm*64 + mi*16 + lrow)*80 + (k0 + lhi*8)*2);
            ldsm4(addr, afr[buf][mi][0], afr[buf][mi][1], afr[buf][mi][2], afr[buf][mi][3]);
        }
        #pragma unroll
        for (int nt = 0; nt < 4; ++nt){
            unsigned addr = bb + (uint32_t)((k0 + lrow)*272 + (wn*64 + nt*16 + lhi*8)*2);
            unsigned r0,r1,r2,r3;
            ldsm4t(addr, r0,r1,r2,r3);
            bfr[buf][nt*2  ][0]=r0; bfr[buf][nt*2  ][1]=r1;
            bfr[buf][nt*2+1][0]=r2; bfr[buf][nt*2+1][1]=r3;
        }
    };

    float acc[4][8][4] = {};

    #pragma unroll
    for (int s = 0; s < 3; s++){
        load_stage(s, s);
        asm volatile("cp.async.commit_group;");
    }
    asm volatile("cp.async.wait_group 2;");
    __syncthreads();
    ldfr(0, 0, 0);

    for (int c = 0; c < nchunks; ++c){
        int s = c & 3;
        ldfr(s, 1, 1);
        #pragma unroll
        for (int mi = 0; mi < 4; ++mi)
            #pragma unroll
            for (int ni = 0; ni < 8; ++ni)
                mma16816(acc[mi][ni], afr[0][mi], bfr[0][ni]);
        if (c + 3 < nchunks) load_stage((c+3)&3, c+3);
        asm volatile("cp.async.commit_group;");
        if (c + 1 < nchunks){
            asm volatile("cp.async.wait_group 2;");
            __syncthreads();
            ldfr((c+1)&3, 0, 0);
        }
        #pragma unroll
        for (int mi = 0; mi < 4; ++mi)
            #pragma unroll
            for (int ni = 0; ni < 8; ++ni)
                mma16816(acc[mi][ni], afr[1][mi], bfr[1][ni]);
    }

    // epilogue
    int g = lane >> 2, tig = lane & 3;
    #pragma unroll
    for (int mi = 0; mi < 4; ++mi){
        #pragma unroll
        for (int half = 0; half < 2; ++half){
            int row = m0 + wm*64 + mi*16 + g + half*8;
            if (row >= M) continue;
            if constexpr (EPI == 0){
                const int bb2 = n0 >= 384;
                const int hb  = (n0 - bb2*384) >> 7;
                float bqv = bq[row];
                float mv  = mask[bb2*N_ + row];
                float s1 = 0.f, s2 = 0.f;
                #pragma unroll
                for (int ni = 0; ni < 8; ++ni){
                    int c = wn*64 + ni*8 + tig*2;
                    int f = hb*128 + c;
                    float v0 = acc[mi][ni][half*2+0]
                             + bqv*g_uvw[2*F_+f]   + mv*g_uvw[f]   + g_uvw[F_+f];
                    float v1 = acc[mi][ni][half*2+1]
                             + bqv*g_uvw[2*F_+f+1] + mv*g_uvw[f+1] + g_uvw[F_+f+1];
                    *(__half2*)&g_xp[((size_t)bb2*N_ + row)*F_ + f] = __floats2half2_rn(v0, v1);
                    s1 = fmaf(v0, att_src[hb*C_+c], fmaf(v1, att_src[hb*C_+c+1], s1));
                    s2 = fmaf(v0, att_dst[hb*C_+c], fmaf(v1, att_dst[hb*C_+c+1], s2));
                }
                s1 += __shfl_xor_sync(0xffffffffu, s1, 1);
                s1 += __shfl_xor_sync(0xffffffffu, s1, 2);
                s2 += __shfl_xor_sync(0xffffffffu, s2, 1);
                s2 += __shfl_xor_sync(0xffffffffu, s2, 2);
                if (tig == 0){
                    atomicAdd(&g_asrc[((size_t)bb2*N_ + row)*3 + hb], s1);
                    atomicAdd(&g_adst[((size_t)bb2*N_ + row)*3 + hb], s2);
                }
            } else if constexpr (EPI == 2){
                // mm1: row = b*20000 + node; cols 0..127 = dg
                int b = row >= N_;
                int k = row - b*N_;
                #pragma unroll
                for (int ni = 0; ni < 8; ++ni){
                    int c = wn*64 + ni*8 + tig*2;   // dg
                    *(__half2*)&g_xq[(size_t)k*256 + b*128 + c] =
                        __floats2half2_rn(acc[mi][ni][half*2+0], acc[mi][ni][half*2+1]);
                }
            } else {
                // mm2: row = s; col = b*128 + dg
                #pragma unroll
                for (int ni = 0; ni < 8; ++ni){
                    int col = n0 + wn*64 + ni*8 + tig*2;
                    int b = col >= 128;
                    int dg = col - b*128;
                    float* dst = &g_out2[((size_t)b*S_ + row)*DG_ + dg];
                    atomicAdd(&dst[0], acc[mi][ni][half*2+0]);
                    atomicAdd(&dst[1], acc[mi][ni][half*2+1]);
                }
            }
        }
    }
}

// ---------------- CSR ----------------
__global__ void k_count(const int* __restrict__ ei){
    int e = blockIdx.x*blockDim.x + threadIdx.x;
    if (e >= BE_) return;
    int b = e / E_, j = e - b*E_;
    atomicAdd(&g_cnt[ei[E_ + j] + b*N_], 1);
}
__global__ void k_scan(){
    __shared__ int ssum[1024];
    int tid = threadIdx.x;
    const int CH = (BN_ + 1023)/1024;
    int base = tid*CH, s = 0;
    for (int i = 0; i < CH; i++){ int idx = base+i; if (idx < BN_) s += g_cnt[idx]; }
    ssum[tid] = s;
    __syncthreads();
    for (int off = 1; off < 1024; off <<= 1){
        int v = (tid >= off) ? ssum[tid-off] : 0;
        __syncthreads();
        ssum[tid] += v;
        __syncthreads();
    }
    int run = ssum[tid] - s;
    for (int i = 0; i < CH; i++){
        int idx = base+i;
        if (idx < BN_){ g_off[idx] = run; run += g_cnt[idx]; }
    }
    if (tid == 1023) g_off[BN_] = ssum[1023];
}
__global__ void k_scatter(const int* __restrict__ ei){
    int e = blockIdx.x*blockDim.x + threadIdx.x;
    if (e >= BE_) return;
    int b = e / E_, j = e - b*E_;
    int src = ei[j] + b*N_;
    int dst = ei[E_ + j] + b*N_;
    int pos = g_off[dst] + atomicAdd(&g_cur[dst], 1);
    g_esrc[pos] = src;
}

// ---------------- fused aggregation: warp-cooperative alpha -> gat fp16 node-major ----
__global__ void k_aggregate(const float* __restrict__ bias_gat){
    int n = blockIdx.x;
    int tid = threadIdx.x;      // 0..95, covers cols [tid*4, tid*4+4)
    int lane = tid & 31;
    int h = tid >> 5;
    int beg = g_off[n], end = g_off[n+1];
    float ad = g_adst[n*3+h];
    const uint2* xp2 = (const uint2*)g_xp;
    float4 acc = make_float4(0.f,0.f,0.f,0.f);
    float den = 0.f;

    for (int base = beg; base < end; base += 32){
        int nn = end - base; if (nn > 32) nn = 32;
        int   sL = 0;
        float aL = 0.f;
        if (lane < nn){
            sL = g_esrc[base + lane];
            aL = __expf(lrelu(g_asrc[sL*3 + h] + ad));
        }
        int j = 0;
        for (; j + 4 <= nn; j += 4){
            int   s0 = __shfl_sync(0xffffffffu, sL, j+0);
            int   s1 = __shfl_sync(0xffffffffu, sL, j+1);
            int   s2 = __shfl_sync(0xffffffffu, sL, j+2);
            int   s3 = __shfl_sync(0xffffffffu, sL, j+3);
            float a0 = __shfl_sync(0xffffffffu, aL, j+0);
            float a1 = __shfl_sync(0xffffffffu, aL, j+1);
            float a2 = __shfl_sync(0xffffffffu, aL, j+2);
            float a3 = __shfl_sync(0xffffffffu, aL, j+3);
            uint2 r0 = xp2[(size_t)s0*96 + tid];
            uint2 r1 = xp2[(size_t)s1*96 + tid];
            uint2 r2 = xp2[(size_t)s2*96 + tid];
            uint2 r3 = xp2[(size_t)s3*96 + tid];
            float2 v;
            v = __half22float2(*(const __half2*)&r0.x); acc.x=fmaf(v.x,a0,acc.x); acc.y=fmaf(v.y,a0,acc.y);
            v = __half22float2(*(const __half2*)&r0.y); acc.z=fmaf(v.x,a0,acc.z); acc.w=fmaf(v.y,a0,acc.w);
            v = __half22float2(*(const __half2*)&r1.x); acc.x=fmaf(v.x,a1,acc.x); acc.y=fmaf(v.y,a1,acc.y);
            v = __half22float2(*(const __half2*)&r1.y); acc.z=fmaf(v.x,a1,acc.z); acc.w=fmaf(v.y,a1,acc.w);
            v = __half22float2(*(const __half2*)&r2.x); acc.x=fmaf(v.x,a2,acc.x); acc.y=fmaf(v.y,a2,acc.y);
            v = __half22float2(*(const __half2*)&r2.y); acc.z=fmaf(v.x,a2,acc.z); acc.w=fmaf(v.y,a2,acc.w);
            v = __half22float2(*(const __half2*)&r3.x); acc.x=fmaf(v.x,a3,acc.x); acc.y=fmaf(v.y,a3,acc.y);
            v = __half22float2(*(const __half2*)&r3.y); acc.z=fmaf(v.x,a3,acc.z); acc.w=fmaf(v.y,a3,acc.w);
            den += a0 + a1 + a2 + a3;
        }
        for (; j < nn; ++j){
            int   s0 = __shfl_sync(0xffffffffu, sL, j);
            float a0 = __shfl_sync(0xffffffffu, aL, j);
            uint2 r0 = xp2[(size_t)s0*96 + tid];
            float2 v;
            v = __half22float2(*(const __half2*)&r0.x); acc.x=fmaf(v.x,a0,acc.x); acc.y=fmaf(v.y,a0,acc.y);
            v = __half22float2(*(const __half2*)&r0.y); acc.z=fmaf(v.x,a0,acc.z); acc.w=fmaf(v.y,a0,acc.w);
            den += a0;
        }
    }
    // self-loop
    {
        float als = __expf(lrelu(g_asrc[n*3+h] + ad));
        uint2 raw = xp2[(size_t)n*96 + tid];
        float2 v0 = __half22float2(*(const __half2*)&raw.x);
        float2 v1 = __half22float2(*(const __half2*)&raw.y);
        acc.x = fmaf(v0.x, als, acc.x); acc.y = fmaf(v0.y, als, acc.y);
        acc.z = fmaf(v1.x, als, acc.z); acc.w = fmaf(v1.y, als, acc.w);
        den += als;
    }
    float rd = 1.f/den;
    float4 bg = ((const float4*)bias_gat)[tid];
    union { __half bv[4]; uint2 u; } hh;
    hh.bv[0] = __float2half_rn(fmaf(acc.x, rd, bg.x));
    hh.bv[1] = __float2half_rn(fmaf(acc.y, rd, bg.y));
    hh.bv[2] = __float2half_rn(fmaf(acc.z, rd, bg.z));
    hh.bv[3] = __float2half_rn(fmaf(acc.w, rd, bg.w));
    *(uint2*)&g_gat2[(size_t)n*F_ + tid*4] = hh.u;   // node-major [40000,384]
}

// ---------------- final: out = out2 + bproj[s]*wsum[dg] + btemp[dg] ----------------
__global__ void k_fin(float* __restrict__ out,
                      const float* __restrict__ bproj, const float* __restrict__ btemp){
    int i = blockIdx.x*blockDim.x + threadIdx.x;
    if (i >= B_*S_*DG_) return;
    int dg = i & 127;
    int s  = (i >> 7) & 511;
    out[i] = g_out2[i] + bproj[s]*g_wsum[dg] + btemp[dg];
}

// ---------------- host ----------------
extern "C" void kernel_launch(void* const* d_in, const int* in_sizes, int n_in,
                              void* d_out, int out_size){
    const float* x_enc    = (const float*)d_in[0];
    const float* mask     = (const float*)d_in[1];
    const int*   ei       = (const int*)  d_in[2];
    const float* Wq       = (const float*)d_in[3];
    const float* bq       = (const float*)d_in[4];
    const float* Wm       = (const float*)d_in[5];
    const float* bm       = (const float*)d_in[6];
    const float* Wlin     = (const float*)d_in[7];
    const float* att_src  = (const float*)d_in[8];
    const float* att_dst  = (const float*)d_in[9];
    const float* bias_gat = (const float*)d_in[10];
    const float* Wproj    = (const float*)d_in[11];
    const float* bproj    = (const float*)d_in[12];
    const float* Wtemp    = (const float*)d_in[13];
    const float* btemp    = (const float*)d_in[14];
    float* out = (float*)d_out;

    void *pY2=0, *pWq2=0, *pWp2=0, *pG2=0, *pWtT=0, *pXq=0;
    cudaGetSymbolAddress(&pY2,  g_Y2);
    cudaGetSymbolAddress(&pWq2, g_Wq2);
    cudaGetSymbolAddress(&pWp2, g_Wp2);
    cudaGetSymbolAddress(&pG2,  g_gat2);
    cudaGetSymbolAddress(&pWtT, g_WtT);
    cudaGetSymbolAddress(&pXq,  g_xq);

    cudaFuncSetAttribute(k_mma<0>, cudaFuncAttributeMaxDynamicSharedMemorySize, SMEM_MMA);
    cudaFuncSetAttribute(k_mma<2>, cudaFuncAttributeMaxDynamicSharedMemorySize, SMEM_MMA);
    cudaFuncSetAttribute(k_mma<3>, cudaFuncAttributeMaxDynamicSharedMemorySize, SMEM_MMA);

    // 1) mega setup
    k_setup<<<(CVTWQ_T + 255)/256, 256>>>(Wlin, Wm, bm, Wq, Wproj, Wtemp);
    // 2) Y = x_enc @ Wlin^T -> fp16
    k_gemm_bt<<<dim3(F_/64, S_/64, B_), 256>>>(x_enc, S_*D_, Wlin, D_, F_, (__half*)pY2);
    // 3) xp GEMM + fused affine + attention dots
    k_mma<0><<<dim3(NW_/128, (N_ + 127)/128, 1), 128, SMEM_MMA>>>(
        (const __half*)pWq2, 512, N_,
        (const __half*)pY2, NW_,
        16, 1, bq, mask, att_src, att_dst);

    // CSR build
    k_count<<<(BE_ + 255)/256, 256>>>(ei);
    k_scan<<<1, 1024>>>();
    k_scatter<<<(BE_ + 255)/256, 256>>>(ei);

    // aggregation (fused softmax, warp-cooperative alpha) -> gat fp16
    k_aggregate<<<BN_, 96>>>(bias_gat);

    // mm1: xq = gat @ Wtemp^T   [40000,384]x[384,128]
    k_mma<2><<<dim3(1, (BN_ + 127)/128, 1), 128, SMEM_MMA>>>(
        (const __half*)pG2, F_, BN_,
        (const __half*)pWtT, DG_,
        12, 1, nullptr, nullptr, nullptr, nullptr);

    // mm2: out2 += Wproj @ xq   [512,20000]x[20000,256], 36 uneven splits
    k_mma<3><<<dim3(2, S_/128, NSPLIT_MM2), 128, SMEM_MMA>>>(
        (const __half*)pWp2, N_, S_,
        (const __half*)pXq, 256,
        TOTCH_MM2, NSPLIT_MM2, nullptr, nullptr, nullptr, nullptr);

    // final bias add
    k_fin<<<(B_*S_*DG_ + 255)/256, 256>>>(out, bproj, btemp);
}